// round 11
// baseline (speedup 1.0000x reference)
#include <cuda_runtime.h>
#include <cuda_bf16.h>
#include <cstdint>
#include <cstddef>

#define DK 256        // feature dim
#define NC 32         // nodes per chunk (GEMM2 K)
#define ZS 74         // split-K CTAs per d-tile (x2 d-tiles = 148 CTAs)

// ---- smem layout: W resident; nodes/mask/yT double-buffered ----
#define W_STRIDE   528                     // 256 bf16 + 8 pad
#define ND_STRIDE  528
#define MKB_STRIDE 80                      // 32 bf16 + 8 pad (mask, bf16)
#define YT_STRIDE  80                      // 32 bf16 + 8 pad
#define OFF_WT  0
#define OFF_WG  67584                      // 128*528
#define OFF_ND  135168                     // 2 x (32*528  = 16896)
#define OFF_MKB 168960                     // 2 x (256*80  = 20480)
#define OFF_YT  209920                     // 2 x (128*80  = 10240)
#define SMEM_TOTAL 230400
#define ND_BUF  16896
#define MK_BUF  20480
#define YT_BUF  10240

static __device__ __forceinline__ uint32_t smem_u32(const void* p) {
    uint32_t a;
    asm("{ .reg .u64 t; cvta.to.shared.u64 t, %1; cvt.u32.u64 %0, t; }" : "=r"(a) : "l"(p));
    return a;
}

#define LDSM_X4(R, addr)                                                      \
    asm volatile("ldmatrix.sync.aligned.m8n8.x4.shared.b16 {%0,%1,%2,%3}, [%4];" \
                 : "=r"((R)[0]), "=r"((R)[1]), "=r"((R)[2]), "=r"((R)[3])     \
                 : "r"(addr))

#define MMA_BF16(C, A, b0, b1)                                                \
    asm volatile("mma.sync.aligned.m16n8k16.row.col.f32.bf16.bf16.f32 "       \
                 "{%0,%1,%2,%3},{%4,%5,%6,%7},{%8,%9},{%0,%1,%2,%3};"         \
                 : "+f"((C)[0]), "+f"((C)[1]), "+f"((C)[2]), "+f"((C)[3])     \
                 : "r"((A)[0]), "r"((A)[1]), "r"((A)[2]), "r"((A)[3]),        \
                   "r"(b0), "r"(b1))

// mask int {0,1} pair -> packed bf16x2 {1.0 or 0.0}: exact, 2 IMADs
static __device__ __forceinline__ uint32_t cvtm(int x, int y) {
    return (uint32_t)x * 0x3F80u + (uint32_t)y * 0x3F800000u;
}

static __device__ __forceinline__ uint2 pack_bf4(float4 v) {
    __nv_bfloat162 lo = __floats2bfloat162_rn(v.x, v.y);
    __nv_bfloat162 hi = __floats2bfloat162_rn(v.z, v.w);
    uint2 u;
    u.x = *reinterpret_cast<uint32_t*>(&lo);
    u.y = *reinterpret_cast<uint32_t*>(&hi);
    return u;
}

static __device__ __forceinline__ float sigm(float x) { return 1.0f / (1.0f + __expf(-x)); }

// ---------------------------------------------------------------------------
// 2-barrier pipelined fused kernel (grid 74 z x 2 d-tiles):
//  iter it (chunk c): STS nodes(c)+mask(c) [buf it&1] | bar |
//                     GEMM2(c-1) [bufs (it-1)&1] ; GEMM1(c) ; yT(c) epi | bar
// Mask is bf16 in smem -> GEMM2 A-fragments via ldmatrix (no LDS.64/cvt path).
// ---------------------------------------------------------------------------
__global__ __launch_bounds__(512, 1)
void fused_agg(const float* __restrict__ nodes, const int* __restrict__ mask,
               const float* __restrict__ Wt, const float* __restrict__ bt,
               const float* __restrict__ Wg, const float* __restrict__ bg,
               float* __restrict__ out, int Nn)
{
    extern __shared__ char sm[];
    const uint32_t sb = smem_u32(sm);
    const int tid  = threadIdx.x;
    const int lane = tid & 31;
    const int wid  = tid >> 5;
    const int g    = lane >> 2;
    const int tg   = lane & 3;
    const int z    = blockIdx.x;
    const int d0   = blockIdx.y * 128;

    // GEMM1 warp roles: 8 m-warps (16 d rows) x 2 n-warps (16 n cols)
    const int wm = wid & 7;
    const int wn = wid >> 3;
    // GEMM2 warp roles: 8 m-warps (32 b rows) x 2 n-warps (64 d cols)
    const int wm2 = wid >> 1;
    const int wn2 = wid & 1;

    const float bt0 = bt[d0 + wm * 16 + g];
    const float bt1 = bt[d0 + wm * 16 + 8 + g];
    const float bg0 = bg[d0 + wm * 16 + g];
    const float bg1 = bg[d0 + wm * 16 + 8 + g];

    // Persistent GEMM2 accumulators: 2 mf x 8 n8 x 4 = 64 regs
    float acc2[2][8][4];
    #pragma unroll
    for (int i = 0; i < 2; i++)
        #pragma unroll
        for (int j = 0; j < 8; j++)
            #pragma unroll
            for (int q = 0; q < 4; q++) acc2[i][j][q] = 0.f;

    const int NCHK = Nn / NC;   // 200000/32 = 6250 exactly

    // ---- stage resident W (both matrices, f32 -> bf16) ----
    #pragma unroll
    for (int i = 0; i < 16; i++) {
        int f4  = tid + i * 512;
        int row = f4 >> 6;
        int col = (f4 & 63) * 4;
        uint2 a = pack_bf4(*(const float4*)(Wt + (size_t)(d0 + row) * DK + col));
        uint2 b = pack_bf4(*(const float4*)(Wg + (size_t)(d0 + row) * DK + col));
        *(uint2*)(sm + OFF_WT + row * W_STRIDE + col * 2) = a;
        *(uint2*)(sm + OFF_WG + row * W_STRIDE + col * 2) = b;
    }

    // ldmatrix lane addresses (buffer offsets added per iter)
    const uint32_t aWt = sb + OFF_WT + (wm * 16 + (lane & 15)) * W_STRIDE + ((lane >> 4) << 4);
    const uint32_t aWg = aWt + (OFF_WG - OFF_WT);
    const uint32_t bNd = sb + OFF_ND
                       + (wn * 16 + (lane & 7) + ((lane >> 4) << 3)) * ND_STRIDE
                       + (((lane >> 3) & 1) << 4);
    const uint32_t aMK = sb + OFF_MKB + (wm2 * 32 + (lane & 15)) * MKB_STRIDE + ((lane >> 4) << 4);
    const uint32_t bYT = sb + OFF_YT
                       + (wn2 * 64 + (lane & 7) + ((lane >> 4) << 3)) * YT_STRIDE
                       + (((lane >> 3) & 1) << 4);

    // ---- staging maps ----
    const int srow = tid >> 4;                // nodes: 0..31 rows, 16 thr/row
    const int sc16 = tid & 15;
    const int mrow = tid >> 1;                // mask: 0..255 rows, 2 thr/row
    const int mhalf = tid & 1;                // 16-int half of a 32-int row

    uint2    rN[4];                           // nodes, packed bf16 (8 regs)
    uint32_t rM[8];                           // mask,  packed bf16 (8 regs)
    {
        const float* s0 = nodes + (size_t)(z * NC + srow) * DK + sc16 * 4;
        #pragma unroll
        for (int i = 0; i < 4; i++) rN[i] = pack_bf4(*(const float4*)(s0 + i * 64));
        const int* mp = mask + (size_t)mrow * Nn + z * NC + mhalf * 16;
        #pragma unroll
        for (int j = 0; j < 4; j++) {
            int4 v = *(const int4*)(mp + j * 4);
            rM[2 * j]     = cvtm(v.x, v.y);
            rM[2 * j + 1] = cvtm(v.z, v.w);
        }
    }

    int it = 0;
    for (int c = z; c < NCHK; c += ZS, ++it) {
        const uint32_t cb = (uint32_t)(it & 1);
        const uint32_t pb = cb ^ 1u;
        const uint32_t ndb = cb * ND_BUF;
        const uint32_t mkb = cb * MK_BUF, pmk = pb * MK_BUF;
        const uint32_t ytb = cb * YT_BUF, pyt = pb * YT_BUF;

        // ---- STS nodes(c) + mask(c) from prefetched packed regs ----
        {
            char* dn = sm + OFF_ND + ndb + srow * ND_STRIDE + sc16 * 8;
            #pragma unroll
            for (int i = 0; i < 4; i++) *(uint2*)(dn + i * 128) = rN[i];
            char* dm = sm + OFF_MKB + mkb + mrow * MKB_STRIDE + mhalf * 32;
            *(uint4*)dm        = make_uint4(rM[0], rM[1], rM[2], rM[3]);
            *(uint4*)(dm + 16) = make_uint4(rM[4], rM[5], rM[6], rM[7]);
        }
        __syncthreads();   // staged(c) + yT(c-1) visible

        // ---- prefetch chunk c+ZS into regs (hidden under GEMM2+GEMM1) ----
        if (c + ZS < NCHK) {
            const float* s0 = nodes + (size_t)((c + ZS) * NC + srow) * DK + sc16 * 4;
            #pragma unroll
            for (int i = 0; i < 4; i++) rN[i] = pack_bf4(*(const float4*)(s0 + i * 64));
            const int* mp = mask + (size_t)mrow * Nn + (c + ZS) * NC + mhalf * 16;
            #pragma unroll
            for (int j = 0; j < 4; j++) {
                int4 v = *(const int4*)(mp + j * 4);
                rM[2 * j]     = cvtm(v.x, v.y);
                rM[2 * j + 1] = cvtm(v.z, v.w);
            }
        }

        // ---- GEMM2(c-1): acc2 += mask(prev) @ yT(prev)  (warp 32b x 64d) ----
        if (it > 0) {
            #pragma unroll
            for (int ks = 0; ks < 2; ks++) {
                uint32_t A0[4], A1[4];
                LDSM_X4(A0, aMK + pmk + ks * 32);
                LDSM_X4(A1, aMK + pmk + 16 * MKB_STRIDE + ks * 32);
                #pragma unroll
                for (int nf = 0; nf < 4; nf++) {
                    uint32_t Y[4];
                    LDSM_X4(Y, bYT + pyt + nf * 16 * YT_STRIDE + ks * 32);
                    MMA_BF16(acc2[0][2 * nf],     A0, Y[0], Y[1]);
                    MMA_BF16(acc2[0][2 * nf + 1], A0, Y[2], Y[3]);
                    MMA_BF16(acc2[1][2 * nf],     A1, Y[0], Y[1]);
                    MMA_BF16(acc2[1][2 * nf + 1], A1, Y[2], Y[3]);
                }
            }
        }

        // ---- GEMM1(c): yT = W @ nodes^T  (M=128, N=32, K=256) ----
        float aT0[4] = {0,0,0,0}, aT1[4] = {0,0,0,0};
        float aG0[4] = {0,0,0,0}, aG1[4] = {0,0,0,0};
        #pragma unroll
        for (int ks = 0; ks < 16; ks++) {
            uint32_t At[4], Ag[4], Bn[4];
            LDSM_X4(At, aWt + ks * 32);
            LDSM_X4(Ag, aWg + ks * 32);
            LDSM_X4(Bn, bNd + ndb + ks * 32);
            MMA_BF16(aT0, At, Bn[0], Bn[1]);
            MMA_BF16(aT1, At, Bn[2], Bn[3]);
            MMA_BF16(aG0, Ag, Bn[0], Bn[1]);
            MMA_BF16(aG1, Ag, Bn[2], Bn[3]);
        }

        // ---- epilogue: y = (t+bt)*sigmoid(g+bg) -> yT(c) smem bf16 ----
        {
            char* r0 = sm + OFF_YT + ytb + (wm * 16 + g) * YT_STRIDE + (wn * 16 + 2 * tg) * 2;
            char* r1 = r0 + 8 * YT_STRIDE;
            __nv_bfloat162 h;
            h = __floats2bfloat162_rn((aT0[0] + bt0) * sigm(aG0[0] + bg0),
                                      (aT0[1] + bt0) * sigm(aG0[1] + bg0));
            *(uint32_t*)r0 = *reinterpret_cast<uint32_t*>(&h);
            h = __floats2bfloat162_rn((aT0[2] + bt1) * sigm(aG0[2] + bg1),
                                      (aT0[3] + bt1) * sigm(aG0[3] + bg1));
            *(uint32_t*)r1 = *reinterpret_cast<uint32_t*>(&h);
            h = __floats2bfloat162_rn((aT1[0] + bt0) * sigm(aG1[0] + bg0),
                                      (aT1[1] + bt0) * sigm(aG1[1] + bg0));
            *(uint32_t*)(r0 + 16) = *reinterpret_cast<uint32_t*>(&h);
            h = __floats2bfloat162_rn((aT1[2] + bt1) * sigm(aG1[2] + bg1),
                                      (aT1[3] + bt1) * sigm(aG1[3] + bg1));
            *(uint32_t*)(r1 + 16) = *reinterpret_cast<uint32_t*>(&h);
        }
        __syncthreads();   // yT(c)/staging reads done; next iter may overwrite
    }

    // ---- tail: GEMM2 for the last produced chunk ----
    if (it > 0) {
        const uint32_t pb  = (uint32_t)((it - 1) & 1);
        const uint32_t pmk = pb * MK_BUF, pyt = pb * YT_BUF;
        #pragma unroll
        for (int ks = 0; ks < 2; ks++) {
            uint32_t A0[4], A1[4];
            LDSM_X4(A0, aMK + pmk + ks * 32);
            LDSM_X4(A1, aMK + pmk + 16 * MKB_STRIDE + ks * 32);
            #pragma unroll
            for (int nf = 0; nf < 4; nf++) {
                uint32_t Y[4];
                LDSM_X4(Y, bYT + pyt + nf * 16 * YT_STRIDE + ks * 32);
                MMA_BF16(acc2[0][2 * nf],     A0, Y[0], Y[1]);
                MMA_BF16(acc2[0][2 * nf + 1], A0, Y[2], Y[3]);
                MMA_BF16(acc2[1][2 * nf],     A1, Y[0], Y[1]);
                MMA_BF16(acc2[1][2 * nf + 1], A1, Y[2], Y[3]);
            }
        }
    }

    // ---- drain: atomic-accumulate split-K partials ----
    #pragma unroll
    for (int mf = 0; mf < 2; mf++) {
        const int r = wm2 * 32 + mf * 16 + g;
        #pragma unroll
        for (int j = 0; j < 8; j++) {
            const int cb2 = d0 + wn2 * 64 + j * 8 + 2 * tg;
            atomicAdd(out + (size_t)r * DK + cb2,           acc2[mf][j][0]);
            atomicAdd(out + (size_t)r * DK + cb2 + 1,       acc2[mf][j][1]);
            atomicAdd(out + (size_t)(r + 8) * DK + cb2,     acc2[mf][j][2]);
            atomicAdd(out + (size_t)(r + 8) * DK + cb2 + 1, acc2[mf][j][3]);
        }
    }
}

__global__ void kzero(float* __restrict__ o, int n) {
    const int i = blockIdx.x * 256 + threadIdx.x;
    if (i < n) o[i] = 0.f;
}

extern "C" void kernel_launch(void* const* d_in, const int* in_sizes, int n_in,
                              void* d_out, int out_size)
{
    const float* nodes = (const float*)d_in[0];
    const int*   mask  = (const int*)  d_in[1];
    const float* Wt    = (const float*)d_in[2];
    const float* bt    = (const float*)d_in[3];
    const float* Wg    = (const float*)d_in[4];
    const float* bg    = (const float*)d_in[5];
    float* out = (float*)d_out;

    const int Nn = in_sizes[0] / DK;   // 200000

    cudaFuncSetAttribute(fused_agg, cudaFuncAttributeMaxDynamicSharedMemorySize, SMEM_TOTAL);

    kzero<<<(out_size + 255) / 256, 256>>>(out, out_size);
    fused_agg<<<dim3(ZS, 2), 512, SMEM_TOTAL>>>(nodes, mask, Wt, bt, Wg, bg, out, Nn);
}